// round 13
// baseline (speedup 1.0000x reference)
#include <cuda_runtime.h>
#include <cuda_fp16.h>
#include <math.h>
#include <stddef.h>
#include <stdint.h>

// Problem constants
namespace {
constexpr int B_ = 4, T_ = 2048, C_ = 1024, H_ = 4, D_ = 256;
constexpr int M_ = B_ * T_;   // 8192 rows (b*T + t)
constexpr int NG = 4 * C_;    // 4096 gate columns
constexpr int NCH = 4096;     // channels
constexpr int CHK = 64;       // scan chunk length
constexpr int NC = T_ / CHK;  // 32 scan chunks

// GEMM pipeline config (fp16 operands)
constexpr int BK = 64;                      // halfs per k-tile (128 B rows)
constexpr int SSTR = 72;                    // smem row stride in halfs (144 B)
constexpr int STG_HALFS = 2 * 128 * SSTR;   // A + B per stage
constexpr int STG_BYTES = STG_HALFS * 2;    // 36864 B
constexpr int NSTG = 3;
constexpr int DYN_BYTES = NSTG * STG_BYTES; // 110592 B
}

// Scratch (static device globals). Referenced ONLY from device code:
// passing them as kernel args from host binds the host shadow (R5 bug).
__device__ __half g_xc[(size_t)M_ * C_];     // conv+silu output (fp16)
__device__ float g_gates[(size_t)M_ * NG];   // gate activations (fp32)
__device__ float g_h[(size_t)M_ * C_];       // scan output
__device__ __half g_hn[(size_t)M_ * C_];     // normalized (fp16)
__device__ __half g_wx[(size_t)NG * C_];     // fp16 wx_w
__device__ __half g_ow[(size_t)C_ * C_];     // fp16 out_w
__device__ float4 g_summ[NC * NCH];
__device__ float4 g_inc[NC * NCH];
__device__ float g_sum[B_ * H_];
__device__ float g_sqs[B_ * H_];
__device__ float g_ns[B_ * C_];
__device__ float g_nt[B_ * C_];

__device__ __forceinline__ void cp16s(uint32_t smem_addr, const void* gmem) {
    asm volatile("cp.async.cg.shared.global [%0], [%1], 16;"
                 :: "r"(smem_addr), "l"(gmem) : "memory");
}

__device__ __forceinline__ void ldsm_x4a(uint32_t& r0, uint32_t& r1,
                                         uint32_t& r2, uint32_t& r3,
                                         uint32_t addr) {
    asm volatile("ldmatrix.sync.aligned.m8n8.x4.shared.b16 {%0,%1,%2,%3}, [%4];"
                 : "=r"(r0), "=r"(r1), "=r"(r2), "=r"(r3) : "r"(addr));
}

// ---------------------------------------------------------------------------
// fp16 conversion copy into device weight buffers
// ---------------------------------------------------------------------------
template <int WHICH>
__global__ void half_copy_kernel(const float4* __restrict__ src, int n4) {
    __half2* dst = (WHICH == 0) ? (__half2*)g_wx : (__half2*)g_ow;
    int i = blockIdx.x * blockDim.x + threadIdx.x;
    if (i < n4) {
        float4 v = src[i];
        dst[2 * i]     = __floats2half2_rn(v.x, v.y);
        dst[2 * i + 1] = __floats2half2_rn(v.z, v.w);
    }
}

// ---------------------------------------------------------------------------
// Causal depthwise conv (k=4, left pad 3) + bias + SiLU (fp16 output).
// Block 0 also zeroes the GroupNorm stats (consumed much later by scan_c).
// ---------------------------------------------------------------------------
__global__ void conv_silu_kernel(const float* __restrict__ x,
                                 const float* __restrict__ cw,
                                 const float* __restrict__ cb) {
    if (blockIdx.x == 0 && threadIdx.x < B_ * H_) {
        g_sum[threadIdx.x] = 0.f;
        g_sqs[threadIdx.x] = 0.f;
    }
    int idx = blockIdx.x * blockDim.x + threadIdx.x;
    int c = idx & (C_ - 1);
    int m = idx >> 10;
    int t = m & (T_ - 1);
    const float* xp = x + (size_t)m * C_ + c;
    float v = cw[c * 4 + 3] * xp[0];
    if (t >= 1) v += cw[c * 4 + 2] * xp[-C_];
    if (t >= 2) v += cw[c * 4 + 1] * xp[-2 * C_];
    if (t >= 3) v += cw[c * 4 + 0] * xp[-3 * C_];
    v += cb[c];
    g_xc[idx] = __float2half_rn(v / (1.f + __expf(-v)));
}

// ---------------------------------------------------------------------------
// FP16 tensor-core GEMM (mma.sync.m16n8k16, f32 accum):
//   C[m,n] = sum_k A[m,k] * W[n,k]   (both K-contiguous)
// BM=BN=128, BK=64, 256 threads (8 warps, 64x32 warp tiles).
// 3-stage cp.async pipeline, ONE __syncthreads per 64-wide k-tile (16 total);
// 4 independent ldmatrix+HMMA groups per tile let ptxas software-pipeline.
// Stage reuse: tile it+2 -> stage (it+2)%3, last read at it-1, barrier at it.
// EPI=0: A=g_xc, W=g_wx, Co=g_gates (+wx_b, tanh gate2, sigmoid gate3)
// EPI=1: A=g_hn, W=g_ow, Co=param  (+out_b, +residual)
// ---------------------------------------------------------------------------
template <int EPI>
__global__ void __launch_bounds__(256, 2)
gemm_fp16_kernel(const float* __restrict__ bias,
                 const float* __restrict__ resid,
                 float* __restrict__ CoParam,
                 int M, int N, int K) {
    extern __shared__ __align__(16) __half sm[];

    const __half* A = (EPI == 0) ? g_xc : g_hn;
    const __half* W = (EPI == 0) ? g_wx : g_ow;
    float* Co = (EPI == 0) ? g_gates : CoParam;

    const int tid = threadIdx.x;
    const int bm = blockIdx.y * 128;
    const int bn = blockIdx.x * 128;

    const uint32_t smbase = (uint32_t)__cvta_generic_to_shared(sm);

    // ---- loader address precompute (4 x 16B chunks per operand per thread)
    uint32_t cp_a[4], cp_b[4];
    const __half* gm_a[4];
    const __half* gm_b[4];
    {
        const __half* Abase = A + (size_t)bm * K;
        const __half* Bbase = W + (size_t)bn * K;
#pragma unroll
        for (int kc = 0; kc < 4; kc++) {
            int u = tid + 256 * kc;
            int r = u >> 3, j = u & 7;
            cp_a[kc] = smbase + (uint32_t)(r * SSTR + j * 8) * 2;
            cp_b[kc] = cp_a[kc] + 128 * SSTR * 2;
            gm_a[kc] = Abase + (size_t)r * K + j * 8;
            gm_b[kc] = Bbase + (size_t)r * K + j * 8;
        }
    }

#define ISSUE_STAGE(st, kt)                                    \
    do {                                                       \
        uint32_t so_ = (uint32_t)(st) * STG_BYTES;             \
        cp16s(cp_a[0] + so_, gm_a[0] + (kt));                  \
        cp16s(cp_b[0] + so_, gm_b[0] + (kt));                  \
        cp16s(cp_a[1] + so_, gm_a[1] + (kt));                  \
        cp16s(cp_b[1] + so_, gm_b[1] + (kt));                  \
        cp16s(cp_a[2] + so_, gm_a[2] + (kt));                  \
        cp16s(cp_b[2] + so_, gm_b[2] + (kt));                  \
        cp16s(cp_a[3] + so_, gm_a[3] + (kt));                  \
        cp16s(cp_b[3] + so_, gm_b[3] + (kt));                  \
        asm volatile("cp.async.commit_group;" ::: "memory");   \
    } while (0)

    ISSUE_STAGE(0, 0);
    ISSUE_STAGE(1, BK);

    const int wid = tid >> 5;
    const int lane = tid & 31;
    const int wm = (wid & 1) * 64;      // warp row offset
    const int wn = (wid >> 1) * 32;     // warp col offset
    const int qr = lane >> 2;           // 0..7
    const int qc = lane & 3;            // 0..3
    // ldmatrix x4 lane mapping: m0 r0-7 k0, m1 r8-15 k0, m2 r0-7 k8, m3 r8-15 k8
    const int grp = lane >> 3;
    const int row_off = ((grp & 1) << 3) + (lane & 7);
    const int k_off = (grp >> 1) << 3;

    // ---- ldmatrix address precompute (loop-invariant bases)
    uint32_t ld_a[4], ld_b[2];
#pragma unroll
    for (int mt = 0; mt < 4; mt++)
        ld_a[mt] = smbase +
                   (uint32_t)((wm + mt * 16 + row_off) * SSTR + k_off) * 2;
#pragma unroll
    for (int nb = 0; nb < 2; nb++)
        ld_b[nb] = smbase +
                   (uint32_t)((128 + wn + nb * 16 + row_off) * SSTR + k_off) * 2;

    float acc[4][4][4];
#pragma unroll
    for (int i = 0; i < 4; i++)
#pragma unroll
        for (int j = 0; j < 4; j++)
#pragma unroll
            for (int k = 0; k < 4; k++) acc[i][j][k] = 0.f;

    const int nk = K / BK;   // 16
    for (int it = 0; it < nk; it++) {
        if (it + 1 < nk) asm volatile("cp.async.wait_group 1;" ::: "memory");
        else             asm volatile("cp.async.wait_group 0;" ::: "memory");
        __syncthreads();

        // stage (it+2)%3 was last read at iteration it-1 -> safe after barrier
        if (it + 2 < nk) {
            int st = (it + 2) % NSTG;
            ISSUE_STAGE(st, (it + 2) * BK);
        }

        const uint32_t so = (uint32_t)(it % NSTG) * STG_BYTES;

#pragma unroll
        for (int kk0 = 0; kk0 < BK; kk0 += 16) {
            uint32_t af[4][4], bf[4][2];
#pragma unroll
            for (int mt = 0; mt < 4; mt++)
                ldsm_x4a(af[mt][0], af[mt][1], af[mt][2], af[mt][3],
                         ld_a[mt] + so + kk0 * 2);
#pragma unroll
            for (int nb = 0; nb < 2; nb++) {
                uint32_t q0, q1, q2, q3;
                ldsm_x4a(q0, q1, q2, q3, ld_b[nb] + so + kk0 * 2);
                bf[2 * nb][0] = q0; bf[2 * nb + 1][0] = q1;
                bf[2 * nb][1] = q2; bf[2 * nb + 1][1] = q3;
            }
#pragma unroll
            for (int mt = 0; mt < 4; mt++)
#pragma unroll
                for (int nt = 0; nt < 4; nt++) {
                    float* c = acc[mt][nt];
                    asm volatile(
                        "mma.sync.aligned.m16n8k16.row.col.f32.f16.f16.f32 "
                        "{%0,%1,%2,%3}, {%4,%5,%6,%7}, {%8,%9}, {%0,%1,%2,%3};"
                        : "+f"(c[0]), "+f"(c[1]), "+f"(c[2]), "+f"(c[3])
                        : "r"(af[mt][0]), "r"(af[mt][1]), "r"(af[mt][2]), "r"(af[mt][3]),
                          "r"(bf[nt][0]), "r"(bf[nt][1]));
                }
        }
    }
#undef ISSUE_STAGE

    // Epilogue. Within a block the gate index (col>>10) is uniform.
    const int gate = bn >> 10;
#pragma unroll
    for (int mt = 0; mt < 4; mt++) {
#pragma unroll
        for (int nt = 0; nt < 4; nt++) {
            int r0 = bm + wm + mt * 16 + qr;
            int cc = bn + wn + nt * 8 + 2 * qc;
            float2 bb = *(const float2*)(&bias[cc]);
            float v0 = acc[mt][nt][0] + bb.x;
            float v1 = acc[mt][nt][1] + bb.y;
            float v2 = acc[mt][nt][2] + bb.x;
            float v3 = acc[mt][nt][3] + bb.y;
            size_t o0 = (size_t)r0 * N + cc;
            size_t o1 = (size_t)(r0 + 8) * N + cc;
            if (EPI == 0) {
                if (gate == 2) {          // z gate: tanh
                    v0 = tanhf(v0); v1 = tanhf(v1);
                    v2 = tanhf(v2); v3 = tanhf(v3);
                } else if (gate == 3) {   // o gate: sigmoid
                    v0 = __fdividef(1.f, 1.f + __expf(-v0));
                    v1 = __fdividef(1.f, 1.f + __expf(-v1));
                    v2 = __fdividef(1.f, 1.f + __expf(-v2));
                    v3 = __fdividef(1.f, 1.f + __expf(-v3));
                }
            } else {
                float2 r0v = *(const float2*)(&resid[o0]);
                float2 r1v = *(const float2*)(&resid[o1]);
                v0 += r0v.x; v1 += r0v.y;
                v2 += r1v.x; v3 += r1v.y;
            }
            *(float2*)(&Co[o0]) = make_float2(v0, v1);
            *(float2*)(&Co[o1]) = make_float2(v2, v3);
        }
    }
}

// ---------------------------------------------------------------------------
// Chunked parallel sLSTM scan (pair trick: 1 exp per step)
// ---------------------------------------------------------------------------
__global__ void __launch_bounds__(128) scan_a_kernel() {
    int ch = blockIdx.x * 128 + threadIdx.x;
    int ck = blockIdx.y;
    int b = ch >> 10, hd = ch & 1023;
    const float* Gp = g_gates + (size_t)b * T_ * NG + (size_t)ck * CHK * NG + hd;

    float F = 0.f, G = -3e38f, Pz = 0.f, Pn = 0.f;
#pragma unroll 4
    for (int j = 0; j < CHK; j++) {
        const float* p = Gp + (size_t)j * NG;
        float ig = p[0], fg = p[C_], zg = p[2 * C_];
        float u = fg + G - ig;
        float mn = ig + fmaxf(u, 0.f);
        float e = __expf(-fabsf(u));
        float ip = (u >= 0.f) ? e : 1.f;
        float fp = (u >= 0.f) ? 1.f : e;
        Pz = fp * Pz + ip * zg;
        Pn = fp * Pn + ip;
        G = mn;
        F += fg;
    }
    g_summ[ck * NCH + ch] = make_float4(F, G, Pz, Pn);
}

__global__ void __launch_bounds__(128) scan_b_kernel() {
    int ch = blockIdx.x * 128 + threadIdx.x;
    float c = 0.f, n = 1.f, m = 0.f;
#pragma unroll
    for (int j = 0; j < NC; j++) {
        g_inc[j * NCH + ch] = make_float4(c, n, m, 0.f);
        float4 s = g_summ[j * NCH + ch];
        float u = m + s.x - s.y;
        float mo = s.y + fmaxf(u, 0.f);
        float e = __expf(-fabsf(u));
        float a1 = (u >= 0.f) ? 1.f : e;
        float a2 = (u >= 0.f) ? e : 1.f;
        c = a1 * c + a2 * s.z;
        n = a1 * n + a2 * s.w;
        m = mo;
    }
}

__global__ void __launch_bounds__(128) scan_c_kernel() {
    int ch = blockIdx.x * 128 + threadIdx.x;
    int ck = blockIdx.y;
    int b = ch >> 10, hd = ch & 1023;
    const float* Gp = g_gates + (size_t)b * T_ * NG + (size_t)ck * CHK * NG + hd;
    float* hp = g_h + (size_t)b * T_ * C_ + (size_t)ck * CHK * C_ + hd;

    float4 st = g_inc[ck * NCH + ch];
    float c = st.x, n = st.y, m = st.z;
    float s1 = 0.f, s2 = 0.f;

#pragma unroll 4
    for (int j = 0; j < CHK; j++) {
        const float* p = Gp + (size_t)j * NG;
        float ig = p[0], fg = p[C_], zg = p[2 * C_], sg = p[3 * C_];
        float u = fg + m - ig;
        float mn = ig + fmaxf(u, 0.f);
        float e = __expf(-fabsf(u));
        float ip = (u >= 0.f) ? e : 1.f;
        float fp = (u >= 0.f) ? 1.f : e;
        c = fp * c + ip * zg;
        n = fp * n + ip;
        float h = __fdividef(sg * c, n + 1e-6f);
        hp[(size_t)j * C_] = h;
        s1 += h;
        s2 += h * h;
        m = mn;
    }
#pragma unroll
    for (int o = 16; o > 0; o >>= 1) {
        s1 += __shfl_down_sync(0xffffffffu, s1, o);
        s2 += __shfl_down_sync(0xffffffffu, s2, o);
    }
    if ((threadIdx.x & 31) == 0) {
        int grp = (b << 2) + (hd >> 8);
        atomicAdd(&g_sum[grp], s1);
        atomicAdd(&g_sqs[grp], s2);
    }
}

__global__ void prep_norm_kernel(const float* __restrict__ gn_w,
                                 const float* __restrict__ gn_b) {
    int idx = blockIdx.x * blockDim.x + threadIdx.x;
    int b = idx >> 10;
    int c = idx & (C_ - 1);
    int grp = (b << 2) + (c >> 8);
    const float inv_cnt = 1.f / (float)(T_ * D_);
    float mean = g_sum[grp] * inv_cnt;
    float var = g_sqs[grp] * inv_cnt - mean * mean;
    float rstd = rsqrtf(var + 1e-5f);
    float s = rstd * gn_w[c];
    g_ns[idx] = s;
    g_nt[idx] = gn_b[c] - mean * s;
}

__global__ void normalize_kernel() {
    int idx = blockIdx.x * blockDim.x + threadIdx.x;
    int c = idx & (C_ - 1);
    int b = idx >> 21;
    int bc = (b << 10) + c;
    g_hn[idx] = __float2half_rn(g_h[idx] * g_ns[bc] + g_nt[bc]);
}

// ---------------------------------------------------------------------------
// Launch
// ---------------------------------------------------------------------------
extern "C" void kernel_launch(void* const* d_in, const int* in_sizes, int n_in,
                              void* d_out, int out_size) {
    const float* x      = (const float*)d_in[0];
    const float* conv_w = (const float*)d_in[1];
    const float* conv_b = (const float*)d_in[2];
    const float* wx_w   = (const float*)d_in[3];
    const float* wx_b   = (const float*)d_in[4];
    const float* gn_w   = (const float*)d_in[5];
    const float* gn_b   = (const float*)d_in[6];
    const float* out_w  = (const float*)d_in[7];
    const float* out_b  = (const float*)d_in[8];
    float* out = (float*)d_out;

    (void)in_sizes; (void)n_in; (void)out_size;

    cudaFuncSetAttribute(gemm_fp16_kernel<0>,
                         cudaFuncAttributeMaxDynamicSharedMemorySize, DYN_BYTES);
    cudaFuncSetAttribute(gemm_fp16_kernel<1>,
                         cudaFuncAttributeMaxDynamicSharedMemorySize, DYN_BYTES);

    // 0) convert weights to fp16
    half_copy_kernel<0><<<(NG * C_ / 4 + 255) / 256, 256>>>(
        (const float4*)wx_w, NG * C_ / 4);
    half_copy_kernel<1><<<(C_ * C_ / 4 + 255) / 256, 256>>>(
        (const float4*)out_w, C_ * C_ / 4);

    // 1) conv + silu (fp16 output) + stats zeroing
    conv_silu_kernel<<<(M_ * C_) / 256, 256>>>(x, conv_w, conv_b);

    // 2) gates GEMM (+bias, tanh on z, sigmoid on o)
    {
        dim3 g(NG / 128, M_ / 128);
        gemm_fp16_kernel<0><<<g, 256, DYN_BYTES>>>(wx_b, nullptr, nullptr,
                                                   M_, NG, C_);
    }

    // 3) parallel scan (+GroupNorm stats), norm coefficients, apply norm
    {
        dim3 g(NCH / 128, NC);
        scan_a_kernel<<<g, 128>>>();
        scan_b_kernel<<<NCH / 128, 128>>>();
        scan_c_kernel<<<g, 128>>>();
    }
    prep_norm_kernel<<<B_ * C_ / 256, 256>>>(gn_w, gn_b);
    normalize_kernel<<<(M_ * C_) / 256, 256>>>();

    // 4) output GEMM (+bias, +residual) -> d_out
    {
        dim3 g(C_ / 128, M_ / 128);
        gemm_fp16_kernel<1><<<g, 256, DYN_BYTES>>>(out_b, x, out, M_, C_, C_);
    }
}

// round 15
// speedup vs baseline: 1.4398x; 1.4398x over previous
#include <cuda_runtime.h>
#include <cuda_fp16.h>
#include <math.h>
#include <stddef.h>
#include <stdint.h>

// Problem constants
namespace {
constexpr int B_ = 4, T_ = 2048, C_ = 1024, H_ = 4, D_ = 256;
constexpr int M_ = B_ * T_;   // 8192 rows (b*T + t)
constexpr int NG = 4 * C_;    // 4096 gate columns
constexpr int NCH = 4096;     // channels
constexpr int CHK = 64;       // scan chunk length
constexpr int NC = T_ / CHK;  // 32 scan chunks

// GEMM pipeline config (fp16 operands) — proven R11 configuration
constexpr int BK = 32;                      // halfs per k-tile (64 B rows)
constexpr int SSTR = 40;                    // smem row stride in halfs (80 B)
constexpr int STG_HALFS = 2 * 128 * SSTR;   // A + B per stage
constexpr int STG_BYTES = STG_HALFS * 2;
constexpr int NSTG = 4;
constexpr int DYN_BYTES = NSTG * STG_BYTES; // 81920 B
}

// Scratch (static device globals). Referenced ONLY from device code:
// passing them as kernel args from host binds the host shadow (R5 bug).
__device__ __half g_xc[(size_t)M_ * C_];     // conv+silu output (fp16)
__device__ __half g_gates[(size_t)M_ * NG];  // gate activations (fp16)
__device__ __half g_h[(size_t)M_ * C_];      // scan output (fp16, raw h)
__device__ __half g_wx[(size_t)NG * C_];     // fp16 wx_w
__device__ __half g_ow[(size_t)C_ * C_];     // fp16 out_w
__device__ __half g_owb[(size_t)B_ * C_ * C_]; // per-batch GroupNorm-scaled out_w
__device__ float g_bb[B_ * C_];              // per-batch folded bias
__device__ float4 g_summ[NC * NCH];
__device__ float4 g_inc[NC * NCH];
__device__ float g_sum[B_ * H_];
__device__ float g_sqs[B_ * H_];
__device__ float g_ns[B_ * C_];              // GroupNorm scale s (per b,c)
__device__ float g_nt[B_ * C_];              // GroupNorm shift t (per b,c)

__device__ __forceinline__ void cp16s(uint32_t smem_addr, const void* gmem) {
    asm volatile("cp.async.cg.shared.global [%0], [%1], 16;"
                 :: "r"(smem_addr), "l"(gmem) : "memory");
}

__device__ __forceinline__ void ldsm_x4a(uint32_t& r0, uint32_t& r1,
                                         uint32_t& r2, uint32_t& r3,
                                         uint32_t addr) {
    asm volatile("ldmatrix.sync.aligned.m8n8.x4.shared.b16 {%0,%1,%2,%3}, [%4];"
                 : "=r"(r0), "=r"(r1), "=r"(r2), "=r"(r3) : "r"(addr));
}

// ---------------------------------------------------------------------------
// fp16 conversion copy: both weight matrices in one launch
// ---------------------------------------------------------------------------
__global__ void half_copy_kernel(const float4* __restrict__ wx,
                                 const float4* __restrict__ ow) {
    int i = blockIdx.x * blockDim.x + threadIdx.x;
    const int n_wx = NG * C_ / 4;
    const int n_ow = C_ * C_ / 4;
    if (i < n_wx) {
        float4 v = wx[i];
        __half2* dst = (__half2*)g_wx;
        dst[2 * i]     = __floats2half2_rn(v.x, v.y);
        dst[2 * i + 1] = __floats2half2_rn(v.z, v.w);
    } else if (i < n_wx + n_ow) {
        int j = i - n_wx;
        float4 v = ow[j];
        __half2* dst = (__half2*)g_ow;
        dst[2 * j]     = __floats2half2_rn(v.x, v.y);
        dst[2 * j + 1] = __floats2half2_rn(v.z, v.w);
    }
}

// ---------------------------------------------------------------------------
// Causal depthwise conv (k=4, left pad 3) + bias + SiLU (fp16 output).
// Block 0 also zeroes the GroupNorm stats.
// ---------------------------------------------------------------------------
__global__ void conv_silu_kernel(const float* __restrict__ x,
                                 const float* __restrict__ cw,
                                 const float* __restrict__ cb) {
    if (blockIdx.x == 0 && threadIdx.x < B_ * H_) {
        g_sum[threadIdx.x] = 0.f;
        g_sqs[threadIdx.x] = 0.f;
    }
    int idx = blockIdx.x * blockDim.x + threadIdx.x;
    int c = idx & (C_ - 1);
    int m = idx >> 10;
    int t = m & (T_ - 1);
    const float* xp = x + (size_t)m * C_ + c;
    float v = cw[c * 4 + 3] * xp[0];
    if (t >= 1) v += cw[c * 4 + 2] * xp[-C_];
    if (t >= 2) v += cw[c * 4 + 1] * xp[-2 * C_];
    if (t >= 3) v += cw[c * 4 + 0] * xp[-3 * C_];
    v += cb[c];
    g_xc[idx] = __float2half_rn(v / (1.f + __expf(-v)));
}

// ---------------------------------------------------------------------------
// FP16 tensor-core GEMM (mma.sync.m16n8k16, f32 accum):
//   C[m,n] = sum_k A[m,k] * W[n,k]   (both K-contiguous)
// BM=BN=128, BK=32, 256 threads (8 warps, 64x32 warp tiles).
// 4-stage cp.async pipeline, one __syncthreads per k-tile (R11 config).
// EPI=0: A=g_xc, W=g_wx, out fp16 g_gates (+wx_b, tanh gate2, sigmoid gate3)
// EPI=1: A=g_h, W=g_owb[b] (GroupNorm folded), out fp32 param (+g_bb[b], +x)
// ---------------------------------------------------------------------------
template <int EPI>
__global__ void __launch_bounds__(256, 2)
gemm_fp16_kernel(const float* __restrict__ biasParam,
                 const float* __restrict__ resid,
                 float* __restrict__ CoParam,
                 int M, int N, int K) {
    extern __shared__ __align__(16) __half sm[];

    const int tid = threadIdx.x;
    const int bm = blockIdx.y * 128;
    const int bn = blockIdx.x * 128;
    const int batch = bm >> 11;          // row / T_  (used by EPI=1)

    const __half* A = (EPI == 0) ? g_xc : g_h;
    const __half* W = (EPI == 0) ? g_wx : (g_owb + (size_t)batch * C_ * C_);
    const float* bias = (EPI == 0) ? biasParam : (g_bb + batch * C_);

    const uint32_t smbase = (uint32_t)__cvta_generic_to_shared(sm);

    // ---- loader address precompute (2 x 16B chunks per operand per thread)
    uint32_t cp_a[2], cp_b[2];
    const __half* gm_a[2];
    const __half* gm_b[2];
    {
        const __half* Abase = A + (size_t)bm * K;
        const __half* Bbase = W + (size_t)bn * K;
#pragma unroll
        for (int kc = 0; kc < 2; kc++) {
            int u = tid + 256 * kc;
            int r = u >> 2, j = u & 3;
            cp_a[kc] = smbase + (uint32_t)(r * SSTR + j * 8) * 2;
            cp_b[kc] = cp_a[kc] + 128 * SSTR * 2;
            gm_a[kc] = Abase + (size_t)r * K + j * 8;
            gm_b[kc] = Bbase + (size_t)r * K + j * 8;
        }
    }

#define ISSUE_STAGE(st, kt)                                    \
    do {                                                       \
        uint32_t so_ = (uint32_t)(st) * STG_BYTES;             \
        cp16s(cp_a[0] + so_, gm_a[0] + (kt));                  \
        cp16s(cp_b[0] + so_, gm_b[0] + (kt));                  \
        cp16s(cp_a[1] + so_, gm_a[1] + (kt));                  \
        cp16s(cp_b[1] + so_, gm_b[1] + (kt));                  \
        asm volatile("cp.async.commit_group;" ::: "memory");   \
    } while (0)

    ISSUE_STAGE(0, 0);
    ISSUE_STAGE(1, BK);
    ISSUE_STAGE(2, 2 * BK);

    const int wid = tid >> 5;
    const int lane = tid & 31;
    const int wm = (wid & 1) * 64;      // warp row offset
    const int wn = (wid >> 1) * 32;     // warp col offset
    const int qr = lane >> 2;           // 0..7
    const int qc = lane & 3;            // 0..3
    const int grp = lane >> 3;
    const int row_off = ((grp & 1) << 3) + (lane & 7);
    const int k_off = (grp >> 1) << 3;

    uint32_t ld_a[4], ld_b[2];
#pragma unroll
    for (int mt = 0; mt < 4; mt++)
        ld_a[mt] = smbase +
                   (uint32_t)((wm + mt * 16 + row_off) * SSTR + k_off) * 2;
#pragma unroll
    for (int nb = 0; nb < 2; nb++)
        ld_b[nb] = smbase +
                   (uint32_t)((128 + wn + nb * 16 + row_off) * SSTR + k_off) * 2;

    float acc[4][4][4];
#pragma unroll
    for (int i = 0; i < 4; i++)
#pragma unroll
        for (int j = 0; j < 4; j++)
#pragma unroll
            for (int k = 0; k < 4; k++) acc[i][j][k] = 0.f;

    const int nk = K / BK;
    for (int it = 0; it < nk; it++) {
        const int allow = nk - 1 - it;
        if (allow >= 2)      asm volatile("cp.async.wait_group 2;" ::: "memory");
        else if (allow == 1) asm volatile("cp.async.wait_group 1;" ::: "memory");
        else                 asm volatile("cp.async.wait_group 0;" ::: "memory");
        __syncthreads();

        if (it + 3 < nk) ISSUE_STAGE((it + 3) & (NSTG - 1), (it + 3) * BK);

        const uint32_t so = (uint32_t)(it & (NSTG - 1)) * STG_BYTES;

#pragma unroll
        for (int kk0 = 0; kk0 < BK; kk0 += 16) {
            uint32_t af[4][4], bf[4][2];
#pragma unroll
            for (int mt = 0; mt < 4; mt++)
                ldsm_x4a(af[mt][0], af[mt][1], af[mt][2], af[mt][3],
                         ld_a[mt] + so + kk0 * 2);
#pragma unroll
            for (int nb = 0; nb < 2; nb++) {
                uint32_t q0, q1, q2, q3;
                ldsm_x4a(q0, q1, q2, q3, ld_b[nb] + so + kk0 * 2);
                bf[2 * nb][0] = q0; bf[2 * nb + 1][0] = q1;
                bf[2 * nb][1] = q2; bf[2 * nb + 1][1] = q3;
            }
#pragma unroll
            for (int mt = 0; mt < 4; mt++)
#pragma unroll
                for (int nt = 0; nt < 4; nt++) {
                    float* c = acc[mt][nt];
                    asm volatile(
                        "mma.sync.aligned.m16n8k16.row.col.f32.f16.f16.f32 "
                        "{%0,%1,%2,%3}, {%4,%5,%6,%7}, {%8,%9}, {%0,%1,%2,%3};"
                        : "+f"(c[0]), "+f"(c[1]), "+f"(c[2]), "+f"(c[3])
                        : "r"(af[mt][0]), "r"(af[mt][1]), "r"(af[mt][2]), "r"(af[mt][3]),
                          "r"(bf[nt][0]), "r"(bf[nt][1]));
                }
        }
    }
#undef ISSUE_STAGE

    // Epilogue. Within a block the gate index (col>>10) is uniform.
    const int gate = bn >> 10;
#pragma unroll
    for (int mt = 0; mt < 4; mt++) {
#pragma unroll
        for (int nt = 0; nt < 4; nt++) {
            int r0 = bm + wm + mt * 16 + qr;
            int cc = bn + wn + nt * 8 + 2 * qc;
            float2 bb = *(const float2*)(&bias[cc]);
            float v0 = acc[mt][nt][0] + bb.x;
            float v1 = acc[mt][nt][1] + bb.y;
            float v2 = acc[mt][nt][2] + bb.x;
            float v3 = acc[mt][nt][3] + bb.y;
            size_t o0 = (size_t)r0 * N + cc;
            size_t o1 = (size_t)(r0 + 8) * N + cc;
            if (EPI == 0) {
                if (gate == 2) {          // z gate: tanh
                    v0 = tanhf(v0); v1 = tanhf(v1);
                    v2 = tanhf(v2); v3 = tanhf(v3);
                } else if (gate == 3) {   // o gate: sigmoid
                    v0 = __fdividef(1.f, 1.f + __expf(-v0));
                    v1 = __fdividef(1.f, 1.f + __expf(-v1));
                    v2 = __fdividef(1.f, 1.f + __expf(-v2));
                    v3 = __fdividef(1.f, 1.f + __expf(-v3));
                }
                *(__half2*)(&g_gates[o0]) = __floats2half2_rn(v0, v1);
                *(__half2*)(&g_gates[o1]) = __floats2half2_rn(v2, v3);
            } else {
                float2 r0v = *(const float2*)(&resid[o0]);
                float2 r1v = *(const float2*)(&resid[o1]);
                v0 += r0v.x; v1 += r0v.y;
                v2 += r1v.x; v3 += r1v.y;
                *(float2*)(&CoParam[o0]) = make_float2(v0, v1);
                *(float2*)(&CoParam[o1]) = make_float2(v2, v3);
            }
        }
    }
}

// ---------------------------------------------------------------------------
// Chunked parallel sLSTM scan (pair trick: 1 exp per step). fp16 gate reads.
// ---------------------------------------------------------------------------
__global__ void __launch_bounds__(128) scan_a_kernel() {
    int ch = blockIdx.x * 128 + threadIdx.x;
    int ck = blockIdx.y;
    int b = ch >> 10, hd = ch & 1023;
    const __half* Gp = g_gates + (size_t)b * T_ * NG + (size_t)ck * CHK * NG + hd;

    float F = 0.f, G = -3e38f, Pz = 0.f, Pn = 0.f;
#pragma unroll 4
    for (int j = 0; j < CHK; j++) {
        const __half* p = Gp + (size_t)j * NG;
        float ig = __half2float(p[0]);
        float fg = __half2float(p[C_]);
        float zg = __half2float(p[2 * C_]);
        float u = fg + G - ig;
        float mn = ig + fmaxf(u, 0.f);
        float e = __expf(-fabsf(u));
        float ip = (u >= 0.f) ? e : 1.f;
        float fp = (u >= 0.f) ? 1.f : e;
        Pz = fp * Pz + ip * zg;
        Pn = fp * Pn + ip;
        G = mn;
        F += fg;
    }
    g_summ[ck * NCH + ch] = make_float4(F, G, Pz, Pn);
}

__global__ void __launch_bounds__(128) scan_b_kernel() {
    int ch = blockIdx.x * 128 + threadIdx.x;
    float c = 0.f, n = 1.f, m = 0.f;
#pragma unroll
    for (int j = 0; j < NC; j++) {
        g_inc[j * NCH + ch] = make_float4(c, n, m, 0.f);
        float4 s = g_summ[j * NCH + ch];
        float u = m + s.x - s.y;
        float mo = s.y + fmaxf(u, 0.f);
        float e = __expf(-fabsf(u));
        float a1 = (u >= 0.f) ? 1.f : e;
        float a2 = (u >= 0.f) ? e : 1.f;
        c = a1 * c + a2 * s.z;
        n = a1 * n + a2 * s.w;
        m = mo;
    }
}

__global__ void __launch_bounds__(128) scan_c_kernel() {
    int ch = blockIdx.x * 128 + threadIdx.x;
    int ck = blockIdx.y;
    int b = ch >> 10, hd = ch & 1023;
    const __half* Gp = g_gates + (size_t)b * T_ * NG + (size_t)ck * CHK * NG + hd;
    __half* hp = g_h + (size_t)b * T_ * C_ + (size_t)ck * CHK * C_ + hd;

    float4 st = g_inc[ck * NCH + ch];
    float c = st.x, n = st.y, m = st.z;
    float s1 = 0.f, s2 = 0.f;

#pragma unroll 4
    for (int j = 0; j < CHK; j++) {
        const __half* p = Gp + (size_t)j * NG;
        float ig = __half2float(p[0]);
        float fg = __half2float(p[C_]);
        float zg = __half2float(p[2 * C_]);
        float sg = __half2float(p[3 * C_]);   // pre-sigmoided
        float u = fg + m - ig;
        float mn = ig + fmaxf(u, 0.f);
        float e = __expf(-fabsf(u));
        float ip = (u >= 0.f) ? e : 1.f;
        float fp = (u >= 0.f) ? 1.f : e;
        c = fp * c + ip * zg;
        n = fp * n + ip;
        float h = __fdividef(sg * c, n + 1e-6f);
        hp[(size_t)j * C_] = __float2half_rn(h);
        s1 += h;
        s2 += h * h;
        m = mn;
    }
#pragma unroll
    for (int o = 16; o > 0; o >>= 1) {
        s1 += __shfl_down_sync(0xffffffffu, s1, o);
        s2 += __shfl_down_sync(0xffffffffu, s2, o);
    }
    if ((threadIdx.x & 31) == 0) {
        int grp = (b << 2) + (hd >> 8);
        atomicAdd(&g_sum[grp], s1);
        atomicAdd(&g_sqs[grp], s2);
    }
}

// ---------------------------------------------------------------------------
// GroupNorm scale/shift per (b,c):  hn = h*s + t
// ---------------------------------------------------------------------------
__global__ void prep_norm_kernel(const float* __restrict__ gn_w,
                                 const float* __restrict__ gn_b) {
    int idx = blockIdx.x * blockDim.x + threadIdx.x;
    int b = idx >> 10;
    int c = idx & (C_ - 1);
    int grp = (b << 2) + (c >> 8);
    const float inv_cnt = 1.f / (float)(T_ * D_);
    float mean = g_sum[grp] * inv_cnt;
    float var = g_sqs[grp] * inv_cnt - mean * mean;
    float rstd = rsqrtf(var + 1e-5f);
    float s = rstd * gn_w[c];
    g_ns[idx] = s;
    g_nt[idx] = gn_b[c] - mean * s;
}

// ---------------------------------------------------------------------------
// Fold GroupNorm scale into per-batch out weights: owb[b,n,k] = ow[n,k]*s[b,k]
// ---------------------------------------------------------------------------
__global__ void build_owb_kernel() {
    int idx = blockIdx.x * blockDim.x + threadIdx.x;   // over B_*C_*C_/2
    int k2 = idx & (C_ / 2 - 1);        // half2 index within row
    int n = (idx >> 9) & (C_ - 1);
    int b = idx >> 19;
    __half2 w2 = ((const __half2*)g_ow)[n * (C_ / 2) + k2];
    float2 sf = *(const float2*)(&g_ns[b * C_ + 2 * k2]);
    float2 wf = __half22float2(w2);
    ((__half2*)g_owb)[idx] = __floats2half2_rn(wf.x * sf.x, wf.y * sf.y);
}

// ---------------------------------------------------------------------------
// Folded bias: bb[b,n] = out_b[n] + sum_k t[b,k] * ow[n,k]   (warp per (b,n))
// ---------------------------------------------------------------------------
__global__ void build_bias_kernel(const float* __restrict__ out_w,
                                  const float* __restrict__ out_b) {
    int w = (blockIdx.x * blockDim.x + threadIdx.x) >> 5;   // warp id: 0..4095
    int lane = threadIdx.x & 31;
    int b = w >> 10;
    int n = w & (C_ - 1);
    const float* tw = g_nt + b * C_;
    const float* ow = out_w + (size_t)n * C_;
    float s = 0.f;
#pragma unroll 4
    for (int k = lane; k < C_; k += 32) s += tw[k] * ow[k];
#pragma unroll
    for (int o = 16; o > 0; o >>= 1) s += __shfl_down_sync(0xffffffffu, s, o);
    if (lane == 0) g_bb[w] = s + out_b[n];
}

// ---------------------------------------------------------------------------
// Launch
// ---------------------------------------------------------------------------
extern "C" void kernel_launch(void* const* d_in, const int* in_sizes, int n_in,
                              void* d_out, int out_size) {
    const float* x      = (const float*)d_in[0];
    const float* conv_w = (const float*)d_in[1];
    const float* conv_b = (const float*)d_in[2];
    const float* wx_w   = (const float*)d_in[3];
    const float* wx_b   = (const float*)d_in[4];
    const float* gn_w   = (const float*)d_in[5];
    const float* gn_b   = (const float*)d_in[6];
    const float* out_w  = (const float*)d_in[7];
    const float* out_b  = (const float*)d_in[8];
    float* out = (float*)d_out;

    (void)in_sizes; (void)n_in; (void)out_size;

    cudaFuncSetAttribute(gemm_fp16_kernel<0>,
                         cudaFuncAttributeMaxDynamicSharedMemorySize, DYN_BYTES);
    cudaFuncSetAttribute(gemm_fp16_kernel<1>,
                         cudaFuncAttributeMaxDynamicSharedMemorySize, DYN_BYTES);

    // 0) convert both weight matrices to fp16 (one launch)
    {
        int n4 = (NG * C_ + C_ * C_) / 4;
        half_copy_kernel<<<(n4 + 255) / 256, 256>>>(
            (const float4*)wx_w, (const float4*)out_w);
    }

    // 1) conv + silu (fp16 output) + stats zeroing
    conv_silu_kernel<<<(M_ * C_) / 256, 256>>>(x, conv_w, conv_b);

    // 2) gates GEMM -> fp16 g_gates (+bias, tanh on z, sigmoid on o)
    {
        dim3 g(NG / 128, M_ / 128);
        gemm_fp16_kernel<0><<<g, 256, DYN_BYTES>>>(wx_b, nullptr, nullptr,
                                                   M_, NG, C_);
    }

    // 3) parallel scan (+GroupNorm stats); h stored fp16
    {
        dim3 g(NCH / 128, NC);
        scan_a_kernel<<<g, 128>>>();
        scan_b_kernel<<<NCH / 128, 128>>>();
        scan_c_kernel<<<g, 128>>>();
    }

    // 4) GroupNorm folding: s/t, scaled weights, folded bias
    prep_norm_kernel<<<B_ * C_ / 256, 256>>>(gn_w, gn_b);
    build_owb_kernel<<<(B_ * C_ * C_ / 2) / 256, 256>>>();
    build_bias_kernel<<<(B_ * C_ * 32) / 256, 256>>>(out_w, out_b);

    // 5) output GEMM (GroupNorm folded into weights/bias, +residual) -> d_out
    {
        dim3 g(C_ / 128, M_ / 128);
        gemm_fp16_kernel<1><<<g, 256, DYN_BYTES>>>(nullptr, x, out, M_, C_, C_);
    }
}

// round 17
// speedup vs baseline: 1.4576x; 1.0124x over previous
#include <cuda_runtime.h>
#include <cuda_fp16.h>
#include <math.h>
#include <stddef.h>
#include <stdint.h>

// Problem constants
namespace {
constexpr int B_ = 4, T_ = 2048, C_ = 1024, H_ = 4, D_ = 256;
constexpr int M_ = B_ * T_;   // 8192 rows (b*T + t)
constexpr int NG = 4 * C_;    // 4096 gate columns
constexpr int NCH = 4096;     // channels
constexpr int CHK = 64;       // scan chunk length
constexpr int NC = T_ / CHK;  // 32 scan chunks

// GEMM pipeline config (fp16 operands) — proven R11 configuration (FROZEN)
constexpr int BK = 32;                      // halfs per k-tile (64 B rows)
constexpr int SSTR = 40;                    // smem row stride in halfs (80 B)
constexpr int STG_HALFS = 2 * 128 * SSTR;   // A + B per stage
constexpr int STG_BYTES = STG_HALFS * 2;
constexpr int NSTG = 4;
constexpr int DYN_BYTES = NSTG * STG_BYTES; // 81920 B
}

// Scratch (static device globals). Referenced ONLY from device code:
// passing them as kernel args from host binds the host shadow (R5 bug).
__device__ __half g_xc[(size_t)M_ * C_];     // conv+silu output (fp16)
__device__ __half g_gates[(size_t)M_ * NG];  // gate activations (fp16)
__device__ __half g_h[(size_t)M_ * C_];      // scan output (fp16, raw h)
__device__ __half g_wx[(size_t)NG * C_];     // fp16 wx_w
__device__ __half g_ow[(size_t)C_ * C_];     // fp16 out_w
__device__ __half g_owb[(size_t)B_ * C_ * C_]; // per-batch GroupNorm-scaled out_w
__device__ float g_bb[B_ * C_];              // per-batch folded bias
__device__ float4 g_summ[NC * NCH];
__device__ float4 g_inc[NC * NCH];
__device__ float g_sum[B_ * H_];
__device__ float g_sqs[B_ * H_];
__device__ float g_ns[B_ * C_];              // GroupNorm scale s (per b,c)
__device__ float g_nt[B_ * C_];              // GroupNorm shift t (per b,c)

__device__ __forceinline__ void cp16s(uint32_t smem_addr, const void* gmem) {
    asm volatile("cp.async.cg.shared.global [%0], [%1], 16;"
                 :: "r"(smem_addr), "l"(gmem) : "memory");
}

__device__ __forceinline__ void ldsm_x4a(uint32_t& r0, uint32_t& r1,
                                         uint32_t& r2, uint32_t& r3,
                                         uint32_t addr) {
    asm volatile("ldmatrix.sync.aligned.m8n8.x4.shared.b16 {%0,%1,%2,%3}, [%4];"
                 : "=r"(r0), "=r"(r1), "=r"(r2), "=r"(r3) : "r"(addr));
}

// ---------------------------------------------------------------------------
// fp16 conversion copy: both weight matrices in one launch
// ---------------------------------------------------------------------------
__global__ void half_copy_kernel(const float4* __restrict__ wx,
                                 const float4* __restrict__ ow) {
    int i = blockIdx.x * blockDim.x + threadIdx.x;
    const int n_wx = NG * C_ / 4;
    const int n_ow = C_ * C_ / 4;
    if (i < n_wx) {
        float4 v = wx[i];
        __half2* dst = (__half2*)g_wx;
        dst[2 * i]     = __floats2half2_rn(v.x, v.y);
        dst[2 * i + 1] = __floats2half2_rn(v.z, v.w);
    } else if (i < n_wx + n_ow) {
        int j = i - n_wx;
        float4 v = ow[j];
        __half2* dst = (__half2*)g_ow;
        dst[2 * j]     = __floats2half2_rn(v.x, v.y);
        dst[2 * j + 1] = __floats2half2_rn(v.z, v.w);
    }
}

// ---------------------------------------------------------------------------
// Causal depthwise conv (k=4, left pad 3) + bias + SiLU (fp16 output).
// 4 channels per thread, float4 loads, 8-byte fp16 store.
// Block 0 also zeroes the GroupNorm stats.
// ---------------------------------------------------------------------------
__global__ void conv_silu_kernel(const float* __restrict__ x,
                                 const float* __restrict__ cw,
                                 const float* __restrict__ cb) {
    if (blockIdx.x == 0 && threadIdx.x < B_ * H_) {
        g_sum[threadIdx.x] = 0.f;
        g_sqs[threadIdx.x] = 0.f;
    }
    int i = blockIdx.x * blockDim.x + threadIdx.x;   // over M_*C_/4
    int c = (i << 2) & (C_ - 1);
    int m = i >> 8;               // (i*4) / C_
    int t = m & (T_ - 1);
    const float4* xp = (const float4*)(x + (size_t)m * C_ + c);
    const float4* cwv = (const float4*)cw + c;       // rows c..c+3 (4 taps each)
    float4 w0 = cwv[0], w1 = cwv[1], w2 = cwv[2], w3 = cwv[3];
    float4 bb = *((const float4*)cb + (c >> 2));

    float4 v = make_float4(bb.x, bb.y, bb.z, bb.w);
    float4 x0 = xp[0];
    v.x += w0.w * x0.x; v.y += w1.w * x0.y; v.z += w2.w * x0.z; v.w += w3.w * x0.w;
    if (t >= 1) {
        float4 x1 = xp[-(C_ / 4)];
        v.x += w0.z * x1.x; v.y += w1.z * x1.y; v.z += w2.z * x1.z; v.w += w3.z * x1.w;
    }
    if (t >= 2) {
        float4 x2 = xp[-2 * (C_ / 4)];
        v.x += w0.y * x2.x; v.y += w1.y * x2.y; v.z += w2.y * x2.z; v.w += w3.y * x2.w;
    }
    if (t >= 3) {
        float4 x3 = xp[-3 * (C_ / 4)];
        v.x += w0.x * x3.x; v.y += w1.x * x3.y; v.z += w2.x * x3.z; v.w += w3.x * x3.w;
    }
    float4 s;
    s.x = v.x / (1.f + __expf(-v.x));
    s.y = v.y / (1.f + __expf(-v.y));
    s.z = v.z / (1.f + __expf(-v.z));
    s.w = v.w / (1.f + __expf(-v.w));
    __half2 h0 = __floats2half2_rn(s.x, s.y);
    __half2 h1 = __floats2half2_rn(s.z, s.w);
    *(uint2*)(&g_xc[(size_t)i * 4]) =
        make_uint2(*(uint32_t*)&h0, *(uint32_t*)&h1);
}

// ---------------------------------------------------------------------------
// FP16 tensor-core GEMM (mma.sync.m16n8k16, f32 accum) — FROZEN R11/R15 config
// EPI=0: A=g_xc, W=g_wx, out fp16 g_gates (+wx_b, tanh gate2, sigmoid gate3)
// EPI=1: A=g_h, W=g_owb[b] (GroupNorm folded), out fp32 param (+g_bb[b], +x)
// ---------------------------------------------------------------------------
template <int EPI>
__global__ void __launch_bounds__(256, 2)
gemm_fp16_kernel(const float* __restrict__ biasParam,
                 const float* __restrict__ resid,
                 float* __restrict__ CoParam,
                 int M, int N, int K) {
    extern __shared__ __align__(16) __half sm[];

    const int tid = threadIdx.x;
    const int bm = blockIdx.y * 128;
    const int bn = blockIdx.x * 128;
    const int batch = bm >> 11;          // row / T_  (used by EPI=1)

    const __half* A = (EPI == 0) ? g_xc : g_h;
    const __half* W = (EPI == 0) ? g_wx : (g_owb + (size_t)batch * C_ * C_);
    const float* bias = (EPI == 0) ? biasParam : (g_bb + batch * C_);

    const uint32_t smbase = (uint32_t)__cvta_generic_to_shared(sm);

    uint32_t cp_a[2], cp_b[2];
    const __half* gm_a[2];
    const __half* gm_b[2];
    {
        const __half* Abase = A + (size_t)bm * K;
        const __half* Bbase = W + (size_t)bn * K;
#pragma unroll
        for (int kc = 0; kc < 2; kc++) {
            int u = tid + 256 * kc;
            int r = u >> 2, j = u & 3;
            cp_a[kc] = smbase + (uint32_t)(r * SSTR + j * 8) * 2;
            cp_b[kc] = cp_a[kc] + 128 * SSTR * 2;
            gm_a[kc] = Abase + (size_t)r * K + j * 8;
            gm_b[kc] = Bbase + (size_t)r * K + j * 8;
        }
    }

#define ISSUE_STAGE(st, kt)                                    \
    do {                                                       \
        uint32_t so_ = (uint32_t)(st) * STG_BYTES;             \
        cp16s(cp_a[0] + so_, gm_a[0] + (kt));                  \
        cp16s(cp_b[0] + so_, gm_b[0] + (kt));                  \
        cp16s(cp_a[1] + so_, gm_a[1] + (kt));                  \
        cp16s(cp_b[1] + so_, gm_b[1] + (kt));                  \
        asm volatile("cp.async.commit_group;" ::: "memory");   \
    } while (0)

    ISSUE_STAGE(0, 0);
    ISSUE_STAGE(1, BK);
    ISSUE_STAGE(2, 2 * BK);

    const int wid = tid >> 5;
    const int lane = tid & 31;
    const int wm = (wid & 1) * 64;
    const int wn = (wid >> 1) * 32;
    const int qr = lane >> 2;
    const int qc = lane & 3;
    const int grp = lane >> 3;
    const int row_off = ((grp & 1) << 3) + (lane & 7);
    const int k_off = (grp >> 1) << 3;

    uint32_t ld_a[4], ld_b[2];
#pragma unroll
    for (int mt = 0; mt < 4; mt++)
        ld_a[mt] = smbase +
                   (uint32_t)((wm + mt * 16 + row_off) * SSTR + k_off) * 2;
#pragma unroll
    for (int nb = 0; nb < 2; nb++)
        ld_b[nb] = smbase +
                   (uint32_t)((128 + wn + nb * 16 + row_off) * SSTR + k_off) * 2;

    float acc[4][4][4];
#pragma unroll
    for (int i = 0; i < 4; i++)
#pragma unroll
        for (int j = 0; j < 4; j++)
#pragma unroll
            for (int k = 0; k < 4; k++) acc[i][j][k] = 0.f;

    const int nk = K / BK;
    for (int it = 0; it < nk; it++) {
        const int allow = nk - 1 - it;
        if (allow >= 2)      asm volatile("cp.async.wait_group 2;" ::: "memory");
        else if (allow == 1) asm volatile("cp.async.wait_group 1;" ::: "memory");
        else                 asm volatile("cp.async.wait_group 0;" ::: "memory");
        __syncthreads();

        if (it + 3 < nk) ISSUE_STAGE((it + 3) & (NSTG - 1), (it + 3) * BK);

        const uint32_t so = (uint32_t)(it & (NSTG - 1)) * STG_BYTES;

#pragma unroll
        for (int kk0 = 0; kk0 < BK; kk0 += 16) {
            uint32_t af[4][4], bf[4][2];
#pragma unroll
            for (int mt = 0; mt < 4; mt++)
                ldsm_x4a(af[mt][0], af[mt][1], af[mt][2], af[mt][3],
                         ld_a[mt] + so + kk0 * 2);
#pragma unroll
            for (int nb = 0; nb < 2; nb++) {
                uint32_t q0, q1, q2, q3;
                ldsm_x4a(q0, q1, q2, q3, ld_b[nb] + so + kk0 * 2);
                bf[2 * nb][0] = q0; bf[2 * nb + 1][0] = q1;
                bf[2 * nb][1] = q2; bf[2 * nb + 1][1] = q3;
            }
#pragma unroll
            for (int mt = 0; mt < 4; mt++)
#pragma unroll
                for (int nt = 0; nt < 4; nt++) {
                    float* c = acc[mt][nt];
                    asm volatile(
                        "mma.sync.aligned.m16n8k16.row.col.f32.f16.f16.f32 "
                        "{%0,%1,%2,%3}, {%4,%5,%6,%7}, {%8,%9}, {%0,%1,%2,%3};"
                        : "+f"(c[0]), "+f"(c[1]), "+f"(c[2]), "+f"(c[3])
                        : "r"(af[mt][0]), "r"(af[mt][1]), "r"(af[mt][2]), "r"(af[mt][3]),
                          "r"(bf[nt][0]), "r"(bf[nt][1]));
                }
        }
    }
#undef ISSUE_STAGE

    const int gate = bn >> 10;
#pragma unroll
    for (int mt = 0; mt < 4; mt++) {
#pragma unroll
        for (int nt = 0; nt < 4; nt++) {
            int r0 = bm + wm + mt * 16 + qr;
            int cc = bn + wn + nt * 8 + 2 * qc;
            float2 bb = *(const float2*)(&bias[cc]);
            float v0 = acc[mt][nt][0] + bb.x;
            float v1 = acc[mt][nt][1] + bb.y;
            float v2 = acc[mt][nt][2] + bb.x;
            float v3 = acc[mt][nt][3] + bb.y;
            size_t o0 = (size_t)r0 * N + cc;
            size_t o1 = (size_t)(r0 + 8) * N + cc;
            if (EPI == 0) {
                if (gate == 2) {
                    v0 = tanhf(v0); v1 = tanhf(v1);
                    v2 = tanhf(v2); v3 = tanhf(v3);
                } else if (gate == 3) {
                    v0 = __fdividef(1.f, 1.f + __expf(-v0));
                    v1 = __fdividef(1.f, 1.f + __expf(-v1));
                    v2 = __fdividef(1.f, 1.f + __expf(-v2));
                    v3 = __fdividef(1.f, 1.f + __expf(-v3));
                }
                *(__half2*)(&g_gates[o0]) = __floats2half2_rn(v0, v1);
                *(__half2*)(&g_gates[o1]) = __floats2half2_rn(v2, v3);
            } else {
                float2 r0v = *(const float2*)(&resid[o0]);
                float2 r1v = *(const float2*)(&resid[o1]);
                v0 += r0v.x; v1 += r0v.y;
                v2 += r1v.x; v3 += r1v.y;
                *(float2*)(&CoParam[o0]) = make_float2(v0, v1);
                *(float2*)(&CoParam[o1]) = make_float2(v2, v3);
            }
        }
    }
}

// ---------------------------------------------------------------------------
// Chunked parallel sLSTM scan — 2 channels per thread via half2.
// Channel pairs (2i, 2i+1) never straddle a GroupNorm group boundary.
// ---------------------------------------------------------------------------
__global__ void __launch_bounds__(128) scan_a_kernel() {
    int cp = blockIdx.x * 128 + threadIdx.x;   // channel pair 0..2047
    int ck = blockIdx.y;
    int ch = cp << 1;
    int b = ch >> 10, hd = ch & 1023;
    const __half2* Gp = (const __half2*)
        (g_gates + (size_t)b * T_ * NG + (size_t)ck * CHK * NG + hd);

    float2 F = {0.f, 0.f}, G = {-3e38f, -3e38f};
    float2 Pz = {0.f, 0.f}, Pn = {0.f, 0.f};
#pragma unroll 4
    for (int j = 0; j < CHK; j++) {
        const __half2* p = Gp + (size_t)j * (NG / 2);
        float2 ig = __half22float2(p[0]);
        float2 fg = __half22float2(p[C_ / 2]);
        float2 zg = __half22float2(p[C_]);
        float ux = fg.x + G.x - ig.x;
        float uy = fg.y + G.y - ig.y;
        G.x = ig.x + fmaxf(ux, 0.f);
        G.y = ig.y + fmaxf(uy, 0.f);
        float ex = __expf(-fabsf(ux));
        float ey = __expf(-fabsf(uy));
        float ipx = (ux >= 0.f) ? ex : 1.f, fpx = (ux >= 0.f) ? 1.f : ex;
        float ipy = (uy >= 0.f) ? ey : 1.f, fpy = (uy >= 0.f) ? 1.f : ey;
        Pz.x = fpx * Pz.x + ipx * zg.x;  Pz.y = fpy * Pz.y + ipy * zg.y;
        Pn.x = fpx * Pn.x + ipx;         Pn.y = fpy * Pn.y + ipy;
        F.x += fg.x;  F.y += fg.y;
    }
    g_summ[ck * NCH + ch]     = make_float4(F.x, G.x, Pz.x, Pn.x);
    g_summ[ck * NCH + ch + 1] = make_float4(F.y, G.y, Pz.y, Pn.y);
}

__global__ void __launch_bounds__(128) scan_b_kernel() {
    int ch = blockIdx.x * 128 + threadIdx.x;
    float c = 0.f, n = 1.f, m = 0.f;
#pragma unroll
    for (int j = 0; j < NC; j++) {
        g_inc[j * NCH + ch] = make_float4(c, n, m, 0.f);
        float4 s = g_summ[j * NCH + ch];
        float u = m + s.x - s.y;
        float mo = s.y + fmaxf(u, 0.f);
        float e = __expf(-fabsf(u));
        float a1 = (u >= 0.f) ? 1.f : e;
        float a2 = (u >= 0.f) ? e : 1.f;
        c = a1 * c + a2 * s.z;
        n = a1 * n + a2 * s.w;
        m = mo;
    }
}

__global__ void __launch_bounds__(128) scan_c_kernel() {
    int cp = blockIdx.x * 128 + threadIdx.x;   // channel pair
    int ck = blockIdx.y;
    int ch = cp << 1;
    int b = ch >> 10, hd = ch & 1023;
    const __half2* Gp = (const __half2*)
        (g_gates + (size_t)b * T_ * NG + (size_t)ck * CHK * NG + hd);
    __half2* hp = (__half2*)
        (g_h + (size_t)b * T_ * C_ + (size_t)ck * CHK * C_ + hd);

    float4 st0 = g_inc[ck * NCH + ch];
    float4 st1 = g_inc[ck * NCH + ch + 1];
    float2 c = {st0.x, st1.x}, n = {st0.y, st1.y}, m = {st0.z, st1.z};
    float s1 = 0.f, s2 = 0.f;

#pragma unroll 4
    for (int j = 0; j < CHK; j++) {
        const __half2* p = Gp + (size_t)j * (NG / 2);
        float2 ig = __half22float2(p[0]);
        float2 fg = __half22float2(p[C_ / 2]);
        float2 zg = __half22float2(p[C_]);
        float2 sg = __half22float2(p[3 * (C_ / 2)]);   // pre-sigmoided
        float ux = fg.x + m.x - ig.x;
        float uy = fg.y + m.y - ig.y;
        m.x = ig.x + fmaxf(ux, 0.f);
        m.y = ig.y + fmaxf(uy, 0.f);
        float ex = __expf(-fabsf(ux));
        float ey = __expf(-fabsf(uy));
        float ipx = (ux >= 0.f) ? ex : 1.f, fpx = (ux >= 0.f) ? 1.f : ex;
        float ipy = (uy >= 0.f) ? ey : 1.f, fpy = (uy >= 0.f) ? 1.f : ey;
        c.x = fpx * c.x + ipx * zg.x;  c.y = fpy * c.y + ipy * zg.y;
        n.x = fpx * n.x + ipx;         n.y = fpy * n.y + ipy;
        float hx = __fdividef(sg.x * c.x, n.x + 1e-6f);
        float hy = __fdividef(sg.y * c.y, n.y + 1e-6f);
        hp[(size_t)j * (C_ / 2)] = __floats2half2_rn(hx, hy);
        s1 += hx + hy;
        s2 += hx * hx + hy * hy;
    }
#pragma unroll
    for (int o = 16; o > 0; o >>= 1) {
        s1 += __shfl_down_sync(0xffffffffu, s1, o);
        s2 += __shfl_down_sync(0xffffffffu, s2, o);
    }
    if ((threadIdx.x & 31) == 0) {
        int grp = (b << 2) + (hd >> 8);
        atomicAdd(&g_sum[grp], s1);
        atomicAdd(&g_sqs[grp], s2);
    }
}

// ---------------------------------------------------------------------------
// GroupNorm scale/shift per (b,c):  hn = h*s + t
// ---------------------------------------------------------------------------
__global__ void prep_norm_kernel(const float* __restrict__ gn_w,
                                 const float* __restrict__ gn_b) {
    int idx = blockIdx.x * blockDim.x + threadIdx.x;
    int b = idx >> 10;
    int c = idx & (C_ - 1);
    int grp = (b << 2) + (c >> 8);
    const float inv_cnt = 1.f / (float)(T_ * D_);
    float mean = g_sum[grp] * inv_cnt;
    float var = g_sqs[grp] * inv_cnt - mean * mean;
    float rstd = rsqrtf(var + 1e-5f);
    float s = rstd * gn_w[c];
    g_ns[idx] = s;
    g_nt[idx] = gn_b[c] - mean * s;
}

// ---------------------------------------------------------------------------
// Fold GroupNorm scale into per-batch out weights: owb[b,n,k] = ow[n,k]*s[b,k]
// ---------------------------------------------------------------------------
__global__ void build_owb_kernel() {
    int idx = blockIdx.x * blockDim.x + threadIdx.x;   // over B_*C_*C_/2
    int k2 = idx & (C_ / 2 - 1);
    int n = (idx >> 9) & (C_ - 1);
    int b = idx >> 19;
    __half2 w2 = ((const __half2*)g_ow)[n * (C_ / 2) + k2];
    float2 sf = *(const float2*)(&g_ns[b * C_ + 2 * k2]);
    float2 wf = __half22float2(w2);
    ((__half2*)g_owb)[idx] = __floats2half2_rn(wf.x * sf.x, wf.y * sf.y);
}

// ---------------------------------------------------------------------------
// Folded bias: bb[b,n] = out_b[n] + sum_k t[b,k] * ow[n,k]   (warp per (b,n))
// ---------------------------------------------------------------------------
__global__ void build_bias_kernel(const float* __restrict__ out_w,
                                  const float* __restrict__ out_b) {
    int w = (blockIdx.x * blockDim.x + threadIdx.x) >> 5;
    int lane = threadIdx.x & 31;
    int b = w >> 10;
    int n = w & (C_ - 1);
    const float* tw = g_nt + b * C_;
    const float* ow = out_w + (size_t)n * C_;
    float s = 0.f;
#pragma unroll 4
    for (int k = lane; k < C_; k += 32) s += tw[k] * ow[k];
#pragma unroll
    for (int o = 16; o > 0; o >>= 1) s += __shfl_down_sync(0xffffffffu, s, o);
    if (lane == 0) g_bb[w] = s + out_b[n];
}

// ---------------------------------------------------------------------------
// Launch
// ---------------------------------------------------------------------------
extern "C" void kernel_launch(void* const* d_in, const int* in_sizes, int n_in,
                              void* d_out, int out_size) {
    const float* x      = (const float*)d_in[0];
    const float* conv_w = (const float*)d_in[1];
    const float* conv_b = (const float*)d_in[2];
    const float* wx_w   = (const float*)d_in[3];
    const float* wx_b   = (const float*)d_in[4];
    const float* gn_w   = (const float*)d_in[5];
    const float* gn_b   = (const float*)d_in[6];
    const float* out_w  = (const float*)d_in[7];
    const float* out_b  = (const float*)d_in[8];
    float* out = (float*)d_out;

    (void)in_sizes; (void)n_in; (void)out_size;

    cudaFuncSetAttribute(gemm_fp16_kernel<0>,
                         cudaFuncAttributeMaxDynamicSharedMemorySize, DYN_BYTES);
    cudaFuncSetAttribute(gemm_fp16_kernel<1>,
                         cudaFuncAttributeMaxDynamicSharedMemorySize, DYN_BYTES);

    // 0) convert both weight matrices to fp16 (one launch)
    {
        int n4 = (NG * C_ + C_ * C_) / 4;
        half_copy_kernel<<<(n4 + 255) / 256, 256>>>(
            (const float4*)wx_w, (const float4*)out_w);
    }

    // 1) conv + silu (fp16 output, 4 ch/thread) + stats zeroing
    conv_silu_kernel<<<(M_ * C_ / 4) / 256, 256>>>(x, conv_w, conv_b);

    // 2) gates GEMM -> fp16 g_gates (+bias, tanh on z, sigmoid on o)
    {
        dim3 g(NG / 128, M_ / 128);
        gemm_fp16_kernel<0><<<g, 256, DYN_BYTES>>>(wx_b, nullptr, nullptr,
                                                   M_, NG, C_);
    }

    // 3) parallel scan (+GroupNorm stats); h stored fp16
    {
        dim3 ga(NCH / 2 / 128, NC);
        scan_a_kernel<<<ga, 128>>>();
        scan_b_kernel<<<NCH / 128, 128>>>();
        scan_c_kernel<<<ga, 128>>>();
    }

    // 4) GroupNorm folding: s/t, scaled weights, folded bias
    prep_norm_kernel<<<B_ * C_ / 256, 256>>>(gn_w, gn_b);
    build_owb_kernel<<<(B_ * C_ * C_ / 2) / 256, 256>>>();
    build_bias_kernel<<<(B_ * C_ * 32) / 256, 256>>>(out_w, out_b);

    // 5) output GEMM (GroupNorm folded into weights/bias, +residual) -> d_out
    {
        dim3 g(C_ / 128, M_ / 128);
        gemm_fp16_kernel<1><<<g, 256, DYN_BYTES>>>(nullptr, x, out, M_, C_, C_);
    }
}